// round 2
// baseline (speedup 1.0000x reference)
#include <cuda_runtime.h>
#include <cstdint>

// Problem constants
#define NROWS  32768      // 32 * 1024 rows
#define KCODES 1024
#define DIM    256
#define QELEMS (NROWS * DIM)   // 8388608

// Argmin GEMM tiling
#define BM   64
#define BN   64
#define BK   64
#define XSTR 258
#define BSTR 66
#define SMEM_FLOATS (BM * XSTR + BN * BSTR)
#define SMEM_BYTES  (SMEM_FLOATS * 4)

// ---- scratch (static device globals; no allocation) ----
__device__ int    g_idx[NROWS];
__device__ float  g_se[KCODES];     // fl32 sum e_i^2, sequential order
__device__ float  g_szi[NROWS];     // fl32 sum z_i^2, sequential order (H_A)
__device__ int    g_counts[KCODES];
__device__ double g_ssd;

// packed dual-fp32 FMA (Blackwell FFMA2)
__device__ __forceinline__ void fma2(unsigned long long& acc,
                                     unsigned long long a,
                                     unsigned long long b) {
    asm("fma.rn.f32x2 %0, %1, %2, %0;" : "+l"(acc) : "l"(a), "l"(b));
}
__device__ __forceinline__ float pairsum(unsigned long long v) {
    float lo = __uint_as_float((unsigned)(v & 0xffffffffu));
    float hi = __uint_as_float((unsigned)(v >> 32));
    return lo + hi;
}
__device__ __forceinline__ unsigned long long lds64(const float* p) {
    return *reinterpret_cast<const unsigned long long*>(p);
}

// ---- kernel 1: zero accumulators ----
__global__ void zero_kernel() {
    int t = threadIdx.x;
    if (t < KCODES) g_counts[t] = 0;
    if (t == 0) g_ssd = 0.0;
}

// ---- kernel 2a: per-row sum of squares, SEQUENTIAL fp32 order (hypothesis H_A)
// s = fl(s + fl(x_i * x_i)), i ascending; separate mul/add roundings.
__global__ void rowsq_kernel(const float* __restrict__ x) {
    int row = blockIdx.x * blockDim.x + threadIdx.x;
    if (row >= NROWS) return;
    const float4* p = reinterpret_cast<const float4*>(x) + (size_t)row * (DIM / 4);
    float s = 0.0f;
    #pragma unroll 4
    for (int i = 0; i < DIM / 4; i++) {
        float4 v = __ldg(p + i);
        s = __fadd_rn(s, __fmul_rn(v.x, v.x));
        s = __fadd_rn(s, __fmul_rn(v.y, v.y));
        s = __fadd_rn(s, __fmul_rn(v.z, v.z));
        s = __fadd_rn(s, __fmul_rn(v.w, v.w));
    }
    g_szi[row] = s;
}

// ---- kernel 2b: per-code sum of squares, same sequential order ----
__global__ void codesq_kernel(const float* __restrict__ cb) {
    int code = blockIdx.x * blockDim.x + threadIdx.x;
    if (code >= KCODES) return;
    const float4* p = reinterpret_cast<const float4*>(cb) + (size_t)code * (DIM / 4);
    float s = 0.0f;
    #pragma unroll 4
    for (int i = 0; i < DIM / 4; i++) {
        float4 v = __ldg(p + i);
        s = __fadd_rn(s, __fmul_rn(v.x, v.x));
        s = __fadd_rn(s, __fmul_rn(v.y, v.y));
        s = __fadd_rn(s, __fmul_rn(v.z, v.z));
        s = __fadd_rn(s, __fmul_rn(v.w, v.w));
    }
    g_se[code] = s;
}

// ---- kernel 3: fused distance GEMM + argmin (reference-quantized epilogue) ----
__global__ __launch_bounds__(256, 2)
void argmin_kernel(const float* __restrict__ x, const float* __restrict__ cb) {
    extern __shared__ float sm[];
    float* xs = sm;                 // [BM][XSTR]
    float* bs = sm + BM * XSTR;     // [BN][BSTR]

    const int tid = threadIdx.x;
    const int ty = tid >> 4;        // rows ty*4 .. ty*4+3
    const int tx = tid & 15;        // codes tx + 16*j
    const int rowBase = blockIdx.x * BM;

    // Load x tile [64][256] into shared
    {
        const float4* x4 = reinterpret_cast<const float4*>(x) + (size_t)rowBase * (DIM / 4);
        #pragma unroll
        for (int it = 0; it < 16; it++) {
            int li = it * 256 + tid;
            int r = li >> 6;
            int c4 = li & 63;
            float4 v = x4[(size_t)r * 64 + c4];
            float* dst = xs + r * XSTR + c4 * 4;
            dst[0] = v.x; dst[1] = v.y; dst[2] = v.z; dst[3] = v.w;
        }
    }

    // per-thread row constants szi (4 rows)
    float szi[4];
    #pragma unroll
    for (int i = 0; i < 4; i++) szi[i] = g_szi[rowBase + ty * 4 + i];

    float bestD[4] = {3.0e38f, 3.0e38f, 3.0e38f, 3.0e38f};
    int   bestI[4] = {0, 0, 0, 0};

    const float4* cb4 = reinterpret_cast<const float4*>(cb);

    for (int cn = 0; cn < KCODES / BN; cn++) {
        unsigned long long acc[4][4];
        #pragma unroll
        for (int i = 0; i < 4; i++)
            #pragma unroll
            for (int j = 0; j < 4; j++) acc[i][j] = 0ull;

        for (int kc = 0; kc < DIM / BK; kc++) {
            __syncthreads();
            #pragma unroll
            for (int it = 0; it < 4; it++) {
                int li = it * 256 + tid;
                int cc = li >> 4;
                int c4 = li & 15;
                float4 v = cb4[(size_t)(cn * BN + cc) * 64 + kc * 16 + c4];
                float* dst = bs + cc * BSTR + c4 * 4;
                dst[0] = v.x; dst[1] = v.y; dst[2] = v.z; dst[3] = v.w;
            }
            __syncthreads();

            const float* xp = xs + (ty * 4) * XSTR + kc * BK;
            const float* bp = bs + tx * BSTR;
            #pragma unroll
            for (int k2 = 0; k2 < BK / 2; k2++) {
                unsigned long long a0 = lds64(xp + 0 * XSTR + 2 * k2);
                unsigned long long a1 = lds64(xp + 1 * XSTR + 2 * k2);
                unsigned long long a2 = lds64(xp + 2 * XSTR + 2 * k2);
                unsigned long long a3 = lds64(xp + 3 * XSTR + 2 * k2);
                unsigned long long b0 = lds64(bp + (0 * 16) * BSTR + 2 * k2);
                unsigned long long b1 = lds64(bp + (1 * 16) * BSTR + 2 * k2);
                unsigned long long b2 = lds64(bp + (2 * 16) * BSTR + 2 * k2);
                unsigned long long b3 = lds64(bp + (3 * 16) * BSTR + 2 * k2);
                fma2(acc[0][0], a0, b0); fma2(acc[0][1], a0, b1);
                fma2(acc[0][2], a0, b2); fma2(acc[0][3], a0, b3);
                fma2(acc[1][0], a1, b0); fma2(acc[1][1], a1, b1);
                fma2(acc[1][2], a1, b2); fma2(acc[1][3], a1, b3);
                fma2(acc[2][0], a2, b0); fma2(acc[2][1], a2, b1);
                fma2(acc[2][2], a2, b2); fma2(acc[2][3], a2, b3);
                fma2(acc[3][0], a3, b0); fma2(acc[3][1], a3, b1);
                fma2(acc[3][2], a3, b2); fma2(acc[3][3], a3, b3);
            }
        }

        // Reference-exact epilogue:
        //   r1   = fl(szi + se_c)                (broadcast add rounding)
        //   dist = fl(r1 - fl(2*dot))            (2*dot is exact)
        #pragma unroll
        for (int j = 0; j < 4; j++) {
            int c = cn * BN + tx + 16 * j;
            float se = g_se[c];
            #pragma unroll
            for (int i = 0; i < 4; i++) {
                float r1 = __fadd_rn(szi[i], se);
                float m2 = __fmul_rn(2.0f, pairsum(acc[i][j]));
                float dist = __fsub_rn(r1, m2);
                if (dist < bestD[i]) { bestD[i] = dist; bestI[i] = c; }
                // per-thread codes strictly increase -> '<' keeps lowest idx
            }
        }
    }

    // cross-thread reduction: 16 candidates per row, tie-break lower index
    __syncthreads();
    float* rd = sm;                       // [64][16]
    int*   ri = reinterpret_cast<int*>(sm + BM * 16);
    #pragma unroll
    for (int i = 0; i < 4; i++) {
        rd[(ty * 4 + i) * 16 + tx] = bestD[i];
        ri[(ty * 4 + i) * 16 + tx] = bestI[i];
    }
    __syncthreads();
    if (tid < BM) {
        float bd = rd[tid * 16];
        int   bi = ri[tid * 16];
        #pragma unroll
        for (int t = 1; t < 16; t++) {
            float d2 = rd[tid * 16 + t];
            int   i2 = ri[tid * 16 + t];
            if (d2 < bd || (d2 == bd && i2 < bi)) { bd = d2; bi = i2; }
        }
        g_idx[rowBase + tid] = bi;
    }
}

// ---- kernel 4: gather + straight-through output + loss ssd + histogram ----
__global__ void gather_kernel(const float* __restrict__ x,
                              const float* __restrict__ cb,
                              float* __restrict__ out) {
    __shared__ double warpsum[8];
    int warp = threadIdx.x >> 5, lane = threadIdx.x & 31;
    int row = blockIdx.x * 8 + warp;
    int c = g_idx[row];
    if (lane == 0) atomicAdd(&g_counts[c], 1);

    const float4* x4 = reinterpret_cast<const float4*>(x) + (size_t)row * 64;
    const float4* q4 = reinterpret_cast<const float4*>(cb) + (size_t)c * 64;
    float4* o4 = reinterpret_cast<float4*>(out) + (size_t)row * 64;

    float ssd = 0.f;
    #pragma unroll
    for (int t = 0; t < 2; t++) {
        int j = lane + 32 * t;
        float4 xv = x4[j];
        float4 qv = q4[j];
        float4 d;   // exact reference rounding: d = fl(q - x); o = fl(x + d)
        d.x = __fsub_rn(qv.x, xv.x); d.y = __fsub_rn(qv.y, xv.y);
        d.z = __fsub_rn(qv.z, xv.z); d.w = __fsub_rn(qv.w, xv.w);
        float4 o;
        o.x = __fadd_rn(xv.x, d.x); o.y = __fadd_rn(xv.y, d.y);
        o.z = __fadd_rn(xv.z, d.z); o.w = __fadd_rn(xv.w, d.w);
        o4[j] = o;
        ssd += d.x * d.x + d.y * d.y + d.z * d.z + d.w * d.w;
    }
    #pragma unroll
    for (int off = 16; off > 0; off >>= 1) ssd += __shfl_xor_sync(0xffffffffu, ssd, off);
    if (lane == 0) warpsum[warp] = (double)ssd;
    __syncthreads();
    if (threadIdx.x == 0) {
        double s = 0.0;
        #pragma unroll
        for (int w = 0; w < 8; w++) s += warpsum[w];
        atomicAdd(&g_ssd, s);
    }
}

// ---- kernel 5: finalize loss + perplexity ----
__global__ void finalize_kernel(float* __restrict__ out, int out_size) {
    __shared__ double red[1024];
    int t = threadIdx.x;
    float p = (float)g_counts[t] * (1.0f / (float)NROWS);
    red[t] = (double)(p * logf(p + 1e-10f));
    __syncthreads();
    for (int s = 512; s > 0; s >>= 1) {
        if (t < s) red[t] += red[t + s];
        __syncthreads();
    }
    if (t == 0) {
        float perp = expf(-(float)red[0]);
        float loss = (float)(g_ssd * (1.25 / (double)QELEMS));
        out[out_size - 2] = loss;
        out[out_size - 1] = perp;
    }
}

extern "C" void kernel_launch(void* const* d_in, const int* in_sizes, int n_in,
                              void* d_out, int out_size) {
    const float* x  = (const float*)d_in[0];   // [32,1024,256] f32
    const float* cb = (const float*)d_in[1];   // [1024,256]    f32
    float* out = (float*)d_out;

    cudaFuncSetAttribute(argmin_kernel,
                         cudaFuncAttributeMaxDynamicSharedMemorySize, SMEM_BYTES);

    zero_kernel<<<1, 1024>>>();
    rowsq_kernel<<<NROWS / 256, 256>>>(x);
    codesq_kernel<<<KCODES / 256, 256>>>(cb);
    argmin_kernel<<<NROWS / BM, 256, SMEM_BYTES>>>(x, cb);
    gather_kernel<<<NROWS / 8, 256>>>(x, cb, out);
    finalize_kernel<<<1, 1024>>>(out, out_size);
}

// round 3
// speedup vs baseline: 1.0586x; 1.0586x over previous
#include <cuda_runtime.h>
#include <cstdint>

// Problem constants
#define NROWS  32768
#define KCODES 1024
#define DIM    256
#define QELEMS (NROWS * DIM)

// Argmin GEMM tiling
#define BM   64
#define BN   64
#define BK   64
#define XSTR 260          // multiple of 4 (16B LDS.128 alignment)
#define BSTR 68           // multiple of 4
#define SMEM_FLOATS (BM * XSTR + BN * BSTR)   // 16640 + 4352 = 20992
#define SMEM_BYTES  (SMEM_FLOATS * 4)         // 83968 B

// ---- scratch ----
__device__ int    g_idx[NROWS];
__device__ float  g_se[KCODES];
__device__ float  g_szi[NROWS];
__device__ int    g_counts[KCODES];
__device__ double g_ssd;

__device__ __forceinline__ void fma2(unsigned long long& acc,
                                     unsigned long long a,
                                     unsigned long long b) {
    asm("fma.rn.f32x2 %0, %1, %2, %0;" : "+l"(acc) : "l"(a), "l"(b));
}
__device__ __forceinline__ float pairsum(unsigned long long v) {
    float lo = __uint_as_float((unsigned)(v & 0xffffffffu));
    float hi = __uint_as_float((unsigned)(v >> 32));
    return lo + hi;
}

// ---- kernel 1: zero ----
__global__ void zero_kernel() {
    int t = threadIdx.x;
    if (t < KCODES) g_counts[t] = 0;
    if (t == 0) g_ssd = 0.0;
}

// ---- kernel 2a: per-row sumsq, sequential fp32 order (reference-exact) ----
__global__ void rowsq_kernel(const float* __restrict__ x) {
    int row = blockIdx.x * blockDim.x + threadIdx.x;
    if (row >= NROWS) return;
    const float4* p = reinterpret_cast<const float4*>(x) + (size_t)row * (DIM / 4);
    float s = 0.0f;
    #pragma unroll 4
    for (int i = 0; i < DIM / 4; i++) {
        float4 v = __ldg(p + i);
        s = __fadd_rn(s, __fmul_rn(v.x, v.x));
        s = __fadd_rn(s, __fmul_rn(v.y, v.y));
        s = __fadd_rn(s, __fmul_rn(v.z, v.z));
        s = __fadd_rn(s, __fmul_rn(v.w, v.w));
    }
    g_szi[row] = s;
}

// ---- kernel 2b: per-code sumsq, same order ----
__global__ void codesq_kernel(const float* __restrict__ cb) {
    int code = blockIdx.x * blockDim.x + threadIdx.x;
    if (code >= KCODES) return;
    const float4* p = reinterpret_cast<const float4*>(cb) + (size_t)code * (DIM / 4);
    float s = 0.0f;
    #pragma unroll 4
    for (int i = 0; i < DIM / 4; i++) {
        float4 v = __ldg(p + i);
        s = __fadd_rn(s, __fmul_rn(v.x, v.x));
        s = __fadd_rn(s, __fmul_rn(v.y, v.y));
        s = __fadd_rn(s, __fmul_rn(v.z, v.z));
        s = __fadd_rn(s, __fmul_rn(v.w, v.w));
    }
    g_se[code] = s;
}

// ---- kernel 3: fused distance GEMM + argmin ----
// LDS.128 operands (half the LDS issue of R2), register-prefetched b chunks.
__global__ __launch_bounds__(256, 2)
void argmin_kernel(const float* __restrict__ x, const float* __restrict__ cb) {
    extern __shared__ float sm[];
    float* xs = sm;                 // [BM][XSTR]
    float* bs = sm + BM * XSTR;     // [BN][BSTR] single buffer

    const int tid = threadIdx.x;
    const int ty = tid >> 4;
    const int tx = tid & 15;
    const int rowBase = blockIdx.x * BM;

    // Load x tile [64][256] into shared
    {
        const float4* x4 = reinterpret_cast<const float4*>(x) + (size_t)rowBase * (DIM / 4);
        #pragma unroll
        for (int it = 0; it < 16; it++) {
            int li = it * 256 + tid;
            int r = li >> 6;
            int c4 = li & 63;
            float4 v = x4[(size_t)r * 64 + c4];
            float* dst = xs + r * XSTR + c4 * 4;
            dst[0] = v.x; dst[1] = v.y; dst[2] = v.z; dst[3] = v.w;
        }
    }

    float szi[4];
    #pragma unroll
    for (int i = 0; i < 4; i++) szi[i] = g_szi[rowBase + ty * 4 + i];

    float bestD[4] = {3.0e38f, 3.0e38f, 3.0e38f, 3.0e38f};
    int   bestI[4] = {0, 0, 0, 0};

    const float4* cb4 = reinterpret_cast<const float4*>(cb);

    // b-chunk prefetch lambda-equivalent: chunk c = cn*4 + kc covers
    // codes [cn*64, cn*64+64) x dims [kc*64, kc*64+64)
    float4 pre[4];
    {   // prefetch chunk 0
        #pragma unroll
        for (int it = 0; it < 4; it++) {
            int li = it * 256 + tid;
            int cc = li >> 4;
            int c4 = li & 15;
            pre[it] = __ldg(cb4 + (size_t)cc * 64 + c4);
        }
    }

    unsigned long long acc[4][4];

    for (int c = 0; c < 64; c++) {
        const int cn = c >> 2;
        const int kc = c & 3;

        __syncthreads();            // prior compute done reading bs
        // store prefetched chunk c
        #pragma unroll
        for (int it = 0; it < 4; it++) {
            int li = it * 256 + tid;
            int cc = li >> 4;
            int c4 = li & 15;
            float* dst = bs + cc * BSTR + c4 * 4;
            float4 v = pre[it];
            dst[0] = v.x; dst[1] = v.y; dst[2] = v.z; dst[3] = v.w;
        }
        // issue prefetch of chunk c+1 (overlaps this chunk's compute)
        if (c < 63) {
            int cn2 = (c + 1) >> 2;
            int kc2 = (c + 1) & 3;
            #pragma unroll
            for (int it = 0; it < 4; it++) {
                int li = it * 256 + tid;
                int cc = li >> 4;
                int c4 = li & 15;
                pre[it] = __ldg(cb4 + (size_t)(cn2 * BN + cc) * 64 + kc2 * 16 + c4);
            }
        }
        __syncthreads();            // bs ready

        if (kc == 0) {
            #pragma unroll
            for (int i = 0; i < 4; i++)
                #pragma unroll
                for (int j = 0; j < 4; j++) acc[i][j] = 0ull;
        }

        const float* xp = xs + (ty * 4) * XSTR + kc * BK;
        const float* bp = bs + tx * BSTR;
        #pragma unroll
        for (int k4 = 0; k4 < BK / 4; k4++) {
            ulonglong2 A0 = *reinterpret_cast<const ulonglong2*>(xp + 0 * XSTR + 4 * k4);
            ulonglong2 A1 = *reinterpret_cast<const ulonglong2*>(xp + 1 * XSTR + 4 * k4);
            ulonglong2 A2 = *reinterpret_cast<const ulonglong2*>(xp + 2 * XSTR + 4 * k4);
            ulonglong2 A3 = *reinterpret_cast<const ulonglong2*>(xp + 3 * XSTR + 4 * k4);
            ulonglong2 B0 = *reinterpret_cast<const ulonglong2*>(bp + 0 * 16 * BSTR + 4 * k4);
            ulonglong2 B1 = *reinterpret_cast<const ulonglong2*>(bp + 1 * 16 * BSTR + 4 * k4);
            ulonglong2 B2 = *reinterpret_cast<const ulonglong2*>(bp + 2 * 16 * BSTR + 4 * k4);
            ulonglong2 B3 = *reinterpret_cast<const ulonglong2*>(bp + 3 * 16 * BSTR + 4 * k4);
            fma2(acc[0][0], A0.x, B0.x); fma2(acc[0][0], A0.y, B0.y);
            fma2(acc[0][1], A0.x, B1.x); fma2(acc[0][1], A0.y, B1.y);
            fma2(acc[0][2], A0.x, B2.x); fma2(acc[0][2], A0.y, B2.y);
            fma2(acc[0][3], A0.x, B3.x); fma2(acc[0][3], A0.y, B3.y);
            fma2(acc[1][0], A1.x, B0.x); fma2(acc[1][0], A1.y, B0.y);
            fma2(acc[1][1], A1.x, B1.x); fma2(acc[1][1], A1.y, B1.y);
            fma2(acc[1][2], A1.x, B2.x); fma2(acc[1][2], A1.y, B2.y);
            fma2(acc[1][3], A1.x, B3.x); fma2(acc[1][3], A1.y, B3.y);
            fma2(acc[2][0], A2.x, B0.x); fma2(acc[2][0], A2.y, B0.y);
            fma2(acc[2][1], A2.x, B1.x); fma2(acc[2][1], A2.y, B1.y);
            fma2(acc[2][2], A2.x, B2.x); fma2(acc[2][2], A2.y, B2.y);
            fma2(acc[2][3], A2.x, B3.x); fma2(acc[2][3], A2.y, B3.y);
            fma2(acc[3][0], A3.x, B0.x); fma2(acc[3][0], A3.y, B0.y);
            fma2(acc[3][1], A3.x, B1.x); fma2(acc[3][1], A3.y, B1.y);
            fma2(acc[3][2], A3.x, B2.x); fma2(acc[3][2], A3.y, B2.y);
            fma2(acc[3][3], A3.x, B3.x); fma2(acc[3][3], A3.y, B3.y);
        }

        if (kc == 3) {
            // Reference-exact epilogue: dist = fl(fl(szi+se) - fl(2*dot))
            #pragma unroll
            for (int j = 0; j < 4; j++) {
                int code = cn * BN + tx + 16 * j;
                float se = g_se[code];
                #pragma unroll
                for (int i = 0; i < 4; i++) {
                    float r1 = __fadd_rn(szi[i], se);
                    float m2 = __fmul_rn(2.0f, pairsum(acc[i][j]));
                    float dist = __fsub_rn(r1, m2);
                    if (dist < bestD[i]) { bestD[i] = dist; bestI[i] = code; }
                }
            }
        }
    }

    // cross-thread reduction, tie-break lower index
    __syncthreads();
    float* rd = sm;
    int*   ri = reinterpret_cast<int*>(sm + BM * 16);
    #pragma unroll
    for (int i = 0; i < 4; i++) {
        rd[(ty * 4 + i) * 16 + tx] = bestD[i];
        ri[(ty * 4 + i) * 16 + tx] = bestI[i];
    }
    __syncthreads();
    if (tid < BM) {
        float bd = rd[tid * 16];
        int   bi = ri[tid * 16];
        #pragma unroll
        for (int t = 1; t < 16; t++) {
            float d2 = rd[tid * 16 + t];
            int   i2 = ri[tid * 16 + t];
            if (d2 < bd || (d2 == bd && i2 < bi)) { bd = d2; bi = i2; }
        }
        g_idx[rowBase + tid] = bi;
    }
}

// ---- kernel 4: gather + ST output + ssd + histogram ----
__global__ void gather_kernel(const float* __restrict__ x,
                              const float* __restrict__ cb,
                              float* __restrict__ out) {
    __shared__ double warpsum[8];
    int warp = threadIdx.x >> 5, lane = threadIdx.x & 31;
    int row = blockIdx.x * 8 + warp;
    int c = g_idx[row];
    if (lane == 0) atomicAdd(&g_counts[c], 1);

    const float4* x4 = reinterpret_cast<const float4*>(x) + (size_t)row * 64;
    const float4* q4 = reinterpret_cast<const float4*>(cb) + (size_t)c * 64;
    float4* o4 = reinterpret_cast<float4*>(out) + (size_t)row * 64;

    float ssd = 0.f;
    #pragma unroll
    for (int t = 0; t < 2; t++) {
        int j = lane + 32 * t;
        float4 xv = x4[j];
        float4 qv = q4[j];
        float4 d;
        d.x = __fsub_rn(qv.x, xv.x); d.y = __fsub_rn(qv.y, xv.y);
        d.z = __fsub_rn(qv.z, xv.z); d.w = __fsub_rn(qv.w, xv.w);
        float4 o;
        o.x = __fadd_rn(xv.x, d.x); o.y = __fadd_rn(xv.y, d.y);
        o.z = __fadd_rn(xv.z, d.z); o.w = __fadd_rn(xv.w, d.w);
        o4[j] = o;
        ssd += d.x * d.x + d.y * d.y + d.z * d.z + d.w * d.w;
    }
    #pragma unroll
    for (int off = 16; off > 0; off >>= 1) ssd += __shfl_xor_sync(0xffffffffu, ssd, off);
    if (lane == 0) warpsum[warp] = (double)ssd;
    __syncthreads();
    if (threadIdx.x == 0) {
        double s = 0.0;
        #pragma unroll
        for (int w = 0; w < 8; w++) s += warpsum[w];
        atomicAdd(&g_ssd, s);
    }
}

// ---- kernel 5: finalize ----
__global__ void finalize_kernel(float* __restrict__ out, int out_size) {
    __shared__ double red[1024];
    int t = threadIdx.x;
    float p = (float)g_counts[t] * (1.0f / (float)NROWS);
    red[t] = (double)(p * logf(p + 1e-10f));
    __syncthreads();
    for (int s = 512; s > 0; s >>= 1) {
        if (t < s) red[t] += red[t + s];
        __syncthreads();
    }
    if (t == 0) {
        float perp = expf(-(float)red[0]);
        float loss = (float)(g_ssd * (1.25 / (double)QELEMS));
        out[out_size - 2] = loss;
        out[out_size - 1] = perp;
    }
}

extern "C" void kernel_launch(void* const* d_in, const int* in_sizes, int n_in,
                              void* d_out, int out_size) {
    const float* x  = (const float*)d_in[0];
    const float* cb = (const float*)d_in[1];
    float* out = (float*)d_out;

    cudaFuncSetAttribute(argmin_kernel,
                         cudaFuncAttributeMaxDynamicSharedMemorySize, SMEM_BYTES);

    zero_kernel<<<1, 1024>>>();
    rowsq_kernel<<<NROWS / 256, 256>>>(x);
    codesq_kernel<<<KCODES / 256, 256>>>(cb);
    argmin_kernel<<<NROWS / BM, 256, SMEM_BYTES>>>(x, cb);
    gather_kernel<<<NROWS / 8, 256>>>(x, cb, out);
    finalize_kernel<<<1, 1024>>>(out, out_size);
}

// round 4
// speedup vs baseline: 1.0589x; 1.0003x over previous
#include <cuda_runtime.h>
#include <cstdint>

// Problem constants
#define NROWS  32768
#define KCODES 1024
#define DIM    256
#define QELEMS (NROWS * DIM)

// Argmin GEMM tiling
#define BM   64
#define BN   64
#define BK   64
#define XSTR 260          // multiple of 4 (16B LDS.128 alignment)
#define BSTR 68           // multiple of 4
#define SMEM_FLOATS (BM * XSTR + BN * BSTR)   // 16640 + 4352 = 20992
#define SMEM_BYTES  (SMEM_FLOATS * 4)         // 83968 B

// ---- scratch ----
__device__ int    g_idx[NROWS];
__device__ float  g_se[KCODES];
__device__ float  g_szi[NROWS];
__device__ int    g_counts[KCODES];
__device__ double g_ssd;

__device__ __forceinline__ void fma2(unsigned long long& acc,
                                     unsigned long long a,
                                     unsigned long long b) {
    asm("fma.rn.f32x2 %0, %1, %2, %0;" : "+l"(acc) : "l"(a), "l"(b));
}
__device__ __forceinline__ float pairsum(unsigned long long v) {
    float lo = __uint_as_float((unsigned)(v & 0xffffffffu));
    float hi = __uint_as_float((unsigned)(v >> 32));
    return lo + hi;
}

// ---- kernel 1: zero ----
__global__ void zero_kernel() {
    int t = threadIdx.x;
    if (t < KCODES) g_counts[t] = 0;
    if (t == 0) g_ssd = 0.0;
}

// ---- kernel 2a: per-row sumsq, sequential fp32 order (reference-exact) ----
__global__ void rowsq_kernel(const float* __restrict__ x) {
    int row = blockIdx.x * blockDim.x + threadIdx.x;
    if (row >= NROWS) return;
    const float4* p = reinterpret_cast<const float4*>(x) + (size_t)row * (DIM / 4);
    float s = 0.0f;
    #pragma unroll 4
    for (int i = 0; i < DIM / 4; i++) {
        float4 v = __ldg(p + i);
        s = __fadd_rn(s, __fmul_rn(v.x, v.x));
        s = __fadd_rn(s, __fmul_rn(v.y, v.y));
        s = __fadd_rn(s, __fmul_rn(v.z, v.z));
        s = __fadd_rn(s, __fmul_rn(v.w, v.w));
    }
    g_szi[row] = s;
}

// ---- kernel 2b: per-code sumsq, same order ----
__global__ void codesq_kernel(const float* __restrict__ cb) {
    int code = blockIdx.x * blockDim.x + threadIdx.x;
    if (code >= KCODES) return;
    const float4* p = reinterpret_cast<const float4*>(cb) + (size_t)code * (DIM / 4);
    float s = 0.0f;
    #pragma unroll 4
    for (int i = 0; i < DIM / 4; i++) {
        float4 v = __ldg(p + i);
        s = __fadd_rn(s, __fmul_rn(v.x, v.x));
        s = __fadd_rn(s, __fmul_rn(v.y, v.y));
        s = __fadd_rn(s, __fmul_rn(v.z, v.z));
        s = __fadd_rn(s, __fmul_rn(v.w, v.w));
    }
    g_se[code] = s;
}

// ---- kernel 3: fused distance GEMM + argmin ----
// LDS.128 operands (half the LDS issue of R2), register-prefetched b chunks.
__global__ __launch_bounds__(256, 2)
void argmin_kernel(const float* __restrict__ x, const float* __restrict__ cb) {
    extern __shared__ float sm[];
    float* xs = sm;                 // [BM][XSTR]
    float* bs = sm + BM * XSTR;     // [BN][BSTR] single buffer

    const int tid = threadIdx.x;
    const int ty = tid >> 4;
    const int tx = tid & 15;
    const int rowBase = blockIdx.x * BM;

    // Load x tile [64][256] into shared
    {
        const float4* x4 = reinterpret_cast<const float4*>(x) + (size_t)rowBase * (DIM / 4);
        #pragma unroll
        for (int it = 0; it < 16; it++) {
            int li = it * 256 + tid;
            int r = li >> 6;
            int c4 = li & 63;
            float4 v = x4[(size_t)r * 64 + c4];
            float* dst = xs + r * XSTR + c4 * 4;
            dst[0] = v.x; dst[1] = v.y; dst[2] = v.z; dst[3] = v.w;
        }
    }

    float szi[4];
    #pragma unroll
    for (int i = 0; i < 4; i++) szi[i] = g_szi[rowBase + ty * 4 + i];

    float bestD[4] = {3.0e38f, 3.0e38f, 3.0e38f, 3.0e38f};
    int   bestI[4] = {0, 0, 0, 0};

    const float4* cb4 = reinterpret_cast<const float4*>(cb);

    // b-chunk prefetch lambda-equivalent: chunk c = cn*4 + kc covers
    // codes [cn*64, cn*64+64) x dims [kc*64, kc*64+64)
    float4 pre[4];
    {   // prefetch chunk 0
        #pragma unroll
        for (int it = 0; it < 4; it++) {
            int li = it * 256 + tid;
            int cc = li >> 4;
            int c4 = li & 15;
            pre[it] = __ldg(cb4 + (size_t)cc * 64 + c4);
        }
    }

    unsigned long long acc[4][4];

    for (int c = 0; c < 64; c++) {
        const int cn = c >> 2;
        const int kc = c & 3;

        __syncthreads();            // prior compute done reading bs
        // store prefetched chunk c
        #pragma unroll
        for (int it = 0; it < 4; it++) {
            int li = it * 256 + tid;
            int cc = li >> 4;
            int c4 = li & 15;
            float* dst = bs + cc * BSTR + c4 * 4;
            float4 v = pre[it];
            dst[0] = v.x; dst[1] = v.y; dst[2] = v.z; dst[3] = v.w;
        }
        // issue prefetch of chunk c+1 (overlaps this chunk's compute)
        if (c < 63) {
            int cn2 = (c + 1) >> 2;
            int kc2 = (c + 1) & 3;
            #pragma unroll
            for (int it = 0; it < 4; it++) {
                int li = it * 256 + tid;
                int cc = li >> 4;
                int c4 = li & 15;
                pre[it] = __ldg(cb4 + (size_t)(cn2 * BN + cc) * 64 + kc2 * 16 + c4);
            }
        }
        __syncthreads();            // bs ready

        if (kc == 0) {
            #pragma unroll
            for (int i = 0; i < 4; i++)
                #pragma unroll
                for (int j = 0; j < 4; j++) acc[i][j] = 0ull;
        }

        const float* xp = xs + (ty * 4) * XSTR + kc * BK;
        const float* bp = bs + tx * BSTR;
        #pragma unroll
        for (int k4 = 0; k4 < BK / 4; k4++) {
            ulonglong2 A0 = *reinterpret_cast<const ulonglong2*>(xp + 0 * XSTR + 4 * k4);
            ulonglong2 A1 = *reinterpret_cast<const ulonglong2*>(xp + 1 * XSTR + 4 * k4);
            ulonglong2 A2 = *reinterpret_cast<const ulonglong2*>(xp + 2 * XSTR + 4 * k4);
            ulonglong2 A3 = *reinterpret_cast<const ulonglong2*>(xp + 3 * XSTR + 4 * k4);
            ulonglong2 B0 = *reinterpret_cast<const ulonglong2*>(bp + 0 * 16 * BSTR + 4 * k4);
            ulonglong2 B1 = *reinterpret_cast<const ulonglong2*>(bp + 1 * 16 * BSTR + 4 * k4);
            ulonglong2 B2 = *reinterpret_cast<const ulonglong2*>(bp + 2 * 16 * BSTR + 4 * k4);
            ulonglong2 B3 = *reinterpret_cast<const ulonglong2*>(bp + 3 * 16 * BSTR + 4 * k4);
            fma2(acc[0][0], A0.x, B0.x); fma2(acc[0][0], A0.y, B0.y);
            fma2(acc[0][1], A0.x, B1.x); fma2(acc[0][1], A0.y, B1.y);
            fma2(acc[0][2], A0.x, B2.x); fma2(acc[0][2], A0.y, B2.y);
            fma2(acc[0][3], A0.x, B3.x); fma2(acc[0][3], A0.y, B3.y);
            fma2(acc[1][0], A1.x, B0.x); fma2(acc[1][0], A1.y, B0.y);
            fma2(acc[1][1], A1.x, B1.x); fma2(acc[1][1], A1.y, B1.y);
            fma2(acc[1][2], A1.x, B2.x); fma2(acc[1][2], A1.y, B2.y);
            fma2(acc[1][3], A1.x, B3.x); fma2(acc[1][3], A1.y, B3.y);
            fma2(acc[2][0], A2.x, B0.x); fma2(acc[2][0], A2.y, B0.y);
            fma2(acc[2][1], A2.x, B1.x); fma2(acc[2][1], A2.y, B1.y);
            fma2(acc[2][2], A2.x, B2.x); fma2(acc[2][2], A2.y, B2.y);
            fma2(acc[2][3], A2.x, B3.x); fma2(acc[2][3], A2.y, B3.y);
            fma2(acc[3][0], A3.x, B0.x); fma2(acc[3][0], A3.y, B0.y);
            fma2(acc[3][1], A3.x, B1.x); fma2(acc[3][1], A3.y, B1.y);
            fma2(acc[3][2], A3.x, B2.x); fma2(acc[3][2], A3.y, B2.y);
            fma2(acc[3][3], A3.x, B3.x); fma2(acc[3][3], A3.y, B3.y);
        }

        if (kc == 3) {
            // Reference-exact epilogue: dist = fl(fl(szi+se) - fl(2*dot))
            #pragma unroll
            for (int j = 0; j < 4; j++) {
                int code = cn * BN + tx + 16 * j;
                float se = g_se[code];
                #pragma unroll
                for (int i = 0; i < 4; i++) {
                    float r1 = __fadd_rn(szi[i], se);
                    float m2 = __fmul_rn(2.0f, pairsum(acc[i][j]));
                    float dist = __fsub_rn(r1, m2);
                    if (dist < bestD[i]) { bestD[i] = dist; bestI[i] = code; }
                }
            }
        }
    }

    // cross-thread reduction, tie-break lower index
    __syncthreads();
    float* rd = sm;
    int*   ri = reinterpret_cast<int*>(sm + BM * 16);
    #pragma unroll
    for (int i = 0; i < 4; i++) {
        rd[(ty * 4 + i) * 16 + tx] = bestD[i];
        ri[(ty * 4 + i) * 16 + tx] = bestI[i];
    }
    __syncthreads();
    if (tid < BM) {
        float bd = rd[tid * 16];
        int   bi = ri[tid * 16];
        #pragma unroll
        for (int t = 1; t < 16; t++) {
            float d2 = rd[tid * 16 + t];
            int   i2 = ri[tid * 16 + t];
            if (d2 < bd || (d2 == bd && i2 < bi)) { bd = d2; bi = i2; }
        }
        g_idx[rowBase + tid] = bi;
    }
}

// ---- kernel 4: gather + ST output + ssd + histogram ----
__global__ void gather_kernel(const float* __restrict__ x,
                              const float* __restrict__ cb,
                              float* __restrict__ out) {
    __shared__ double warpsum[8];
    int warp = threadIdx.x >> 5, lane = threadIdx.x & 31;
    int row = blockIdx.x * 8 + warp;
    int c = g_idx[row];
    if (lane == 0) atomicAdd(&g_counts[c], 1);

    const float4* x4 = reinterpret_cast<const float4*>(x) + (size_t)row * 64;
    const float4* q4 = reinterpret_cast<const float4*>(cb) + (size_t)c * 64;
    float4* o4 = reinterpret_cast<float4*>(out) + (size_t)row * 64;

    float ssd = 0.f;
    #pragma unroll
    for (int t = 0; t < 2; t++) {
        int j = lane + 32 * t;
        float4 xv = x4[j];
        float4 qv = q4[j];
        float4 d;
        d.x = __fsub_rn(qv.x, xv.x); d.y = __fsub_rn(qv.y, xv.y);
        d.z = __fsub_rn(qv.z, xv.z); d.w = __fsub_rn(qv.w, xv.w);
        float4 o;
        o.x = __fadd_rn(xv.x, d.x); o.y = __fadd_rn(xv.y, d.y);
        o.z = __fadd_rn(xv.z, d.z); o.w = __fadd_rn(xv.w, d.w);
        o4[j] = o;
        ssd += d.x * d.x + d.y * d.y + d.z * d.z + d.w * d.w;
    }
    #pragma unroll
    for (int off = 16; off > 0; off >>= 1) ssd += __shfl_xor_sync(0xffffffffu, ssd, off);
    if (lane == 0) warpsum[warp] = (double)ssd;
    __syncthreads();
    if (threadIdx.x == 0) {
        double s = 0.0;
        #pragma unroll
        for (int w = 0; w < 8; w++) s += warpsum[w];
        atomicAdd(&g_ssd, s);
    }
}

// ---- kernel 5: finalize ----
__global__ void finalize_kernel(float* __restrict__ out, int out_size) {
    __shared__ double red[1024];
    int t = threadIdx.x;
    float p = (float)g_counts[t] * (1.0f / (float)NROWS);
    red[t] = (double)(p * logf(p + 1e-10f));
    __syncthreads();
    for (int s = 512; s > 0; s >>= 1) {
        if (t < s) red[t] += red[t + s];
        __syncthreads();
    }
    if (t == 0) {
        float perp = expf(-(float)red[0]);
        float loss = (float)(g_ssd * (1.25 / (double)QELEMS));
        out[out_size - 2] = loss;
        out[out_size - 1] = perp;
    }
}

extern "C" void kernel_launch(void* const* d_in, const int* in_sizes, int n_in,
                              void* d_out, int out_size) {
    const float* x  = (const float*)d_in[0];
    const float* cb = (const float*)d_in[1];
    float* out = (float*)d_out;

    cudaFuncSetAttribute(argmin_kernel,
                         cudaFuncAttributeMaxDynamicSharedMemorySize, SMEM_BYTES);

    zero_kernel<<<1, 1024>>>();
    rowsq_kernel<<<NROWS / 256, 256>>>(x);
    codesq_kernel<<<KCODES / 256, 256>>>(cb);
    argmin_kernel<<<NROWS / BM, 256, SMEM_BYTES>>>(x, cb);
    gather_kernel<<<NROWS / 8, 256>>>(x, cb, out);
    finalize_kernel<<<1, 1024>>>(out, out_size);
}

// round 6
// speedup vs baseline: 2.5943x; 2.4500x over previous
#include <cuda_runtime.h>
#include <cstdint>

#define NROWS  32768
#define KCODES 1024
#define DIM    256
#define QELEMS (NROWS * DIM)
#define MARGIN 2.0e-3f

// GEMM smem layout (bytes)
#define GS_A0   0
#define GS_A1   16384
#define GS_B0   32768
#define GS_B1   49152
#define GS_SE   65536
#define GS_RMIN 69632
#define GS_TOTAL 70144

// ---- scratch (static device globals) ----
__device__ int      g_idx[NROWS];
__device__ float    g_se[KCODES];
__device__ float    g_szi[NROWS];
__device__ int      g_counts[KCODES];
__device__ double   g_ssd;
__device__ uint32_t g_af[QELEMS];            // tf32-packed A fragments
__device__ uint32_t g_bf[KCODES * DIM];      // tf32-packed B fragments
__device__ float    g_adist[(size_t)NROWS * KCODES];   // 128MB approx dists
__device__ uint32_t g_amin[NROWS];

__device__ __forceinline__ uint32_t smem_u32(const void* p) {
    uint32_t a;
    asm("{ .reg .u64 t; cvta.to.shared.u64 t, %1; cvt.u32.u64 %0, t; }"
        : "=r"(a) : "l"(p));
    return a;
}
__device__ __forceinline__ uint32_t to_tf32(float f) {
    uint32_t r;
    asm("cvt.rna.tf32.f32 %0, %1;" : "=r"(r) : "f"(f));
    return r;
}
__device__ __forceinline__ void cp16(uint32_t s, const void* g) {
    asm volatile("cp.async.cg.shared.global [%0], [%1], 16;" :: "r"(s), "l"(g));
}
#define CP_COMMIT() asm volatile("cp.async.commit_group;" ::: "memory")
#define CP_WAIT1()  asm volatile("cp.async.wait_group 1;" ::: "memory")
#define CP_WAIT0()  asm volatile("cp.async.wait_group 0;" ::: "memory")

__device__ __forceinline__ void mma_tf32(float* c, const uint4& a, const uint2& b) {
    asm volatile(
        "mma.sync.aligned.m16n8k8.row.col.f32.tf32.tf32.f32 "
        "{%0,%1,%2,%3}, {%4,%5,%6,%7}, {%8,%9}, {%0,%1,%2,%3};"
        : "+f"(c[0]), "+f"(c[1]), "+f"(c[2]), "+f"(c[3])
        : "r"(a.x), "r"(a.y), "r"(a.z), "r"(a.w), "r"(b.x), "r"(b.y));
}

// ---- zero ----
__global__ void zero_kernel() {
    int t = threadIdx.x;
    if (t < KCODES) g_counts[t] = 0;
    if (t == 0) g_ssd = 0.0;
}

// ---- reference-exact sequential fp32 sumsq (DO NOT CHANGE ORDER) ----
__global__ void rowsq_kernel(const float* __restrict__ x) {
    int row = blockIdx.x * blockDim.x + threadIdx.x;
    if (row >= NROWS) return;
    const float4* p = reinterpret_cast<const float4*>(x) + (size_t)row * (DIM / 4);
    float s = 0.0f;
    #pragma unroll 4
    for (int i = 0; i < DIM / 4; i++) {
        float4 v = __ldg(p + i);
        s = __fadd_rn(s, __fmul_rn(v.x, v.x));
        s = __fadd_rn(s, __fmul_rn(v.y, v.y));
        s = __fadd_rn(s, __fmul_rn(v.z, v.z));
        s = __fadd_rn(s, __fmul_rn(v.w, v.w));
    }
    g_szi[row] = s;
}
__global__ void codesq_kernel(const float* __restrict__ cb) {
    int code = blockIdx.x * blockDim.x + threadIdx.x;
    if (code >= KCODES) return;
    const float4* p = reinterpret_cast<const float4*>(cb) + (size_t)code * (DIM / 4);
    float s = 0.0f;
    #pragma unroll 4
    for (int i = 0; i < DIM / 4; i++) {
        float4 v = __ldg(p + i);
        s = __fadd_rn(s, __fmul_rn(v.x, v.x));
        s = __fadd_rn(s, __fmul_rn(v.y, v.y));
        s = __fadd_rn(s, __fmul_rn(v.z, v.z));
        s = __fadd_rn(s, __fmul_rn(v.w, v.w));
    }
    g_se[code] = s;
}

// ---- pack A into mma-fragment order: [mb(256)][ks(32)][mt(8)][lane(32)]{a0..a3}
// a0:(r,c) a1:(r+8,c) a2:(r,c+4) a3:(r+8,c+4); r=lane>>2, c=lane&3 (CUTLASS SM80 16x8x8 maps)
__global__ void packA_kernel(const float* __restrict__ x) {
    int t = blockIdx.x * 256 + threadIdx.x;      // 0 .. 2^21-1 float4s
    int lane = t & 31, mt = (t >> 5) & 7, ks = (t >> 8) & 31, mb = t >> 13;
    int row = mb * 128 + mt * 16 + (lane >> 2);
    int d = ks * 8 + (lane & 3);
    const float* xr = x + (size_t)row * DIM + d;
    uint4 o;
    o.x = to_tf32(xr[0]);
    o.y = to_tf32(xr[8 * DIM]);
    o.z = to_tf32(xr[4]);
    o.w = to_tf32(xr[8 * DIM + 4]);
    reinterpret_cast<uint4*>(g_af)[t] = o;
}

// ---- pack B: [nb(8)][ks(32)][nt(16)][lane(32)]{b0,b1}; b0:(k=lane&3,n=lane>>2) b1:(k+4,n)
__global__ void packB_kernel(const float* __restrict__ cb) {
    int t = blockIdx.x * 256 + threadIdx.x;      // 0 .. 131071 float2s
    int lane = t & 31, nt = (t >> 5) & 15, ks = (t >> 9) & 31, nb = t >> 14;
    int c = nb * 128 + nt * 8 + (lane >> 2);
    int d = ks * 8 + (lane & 3);
    uint2 o;
    o.x = to_tf32(cb[(size_t)c * DIM + d]);
    o.y = to_tf32(cb[(size_t)c * DIM + d + 4]);
    reinterpret_cast<uint2*>(g_bf)[t] = o;
}

// ---- screening GEMM: approx dists for 128 rows x 1024 codes per CTA ----
__global__ __launch_bounds__(256, 2)
void gemm_screen_kernel() {
    extern __shared__ char sm[];
    const uint32_t sb = smem_u32(sm);
    const int tid = threadIdx.x;
    const int w = tid >> 5, lane = tid & 31;
    const int wm = w & 3, wn = w >> 2;
    const int rowBase = blockIdx.x * 128;

    float* se_sm = reinterpret_cast<float*>(sm + GS_SE);
    #pragma unroll
    for (int i = 0; i < 4; i++) se_sm[i * 256 + tid] = g_se[i * 256 + tid];
    uint32_t* rmin = reinterpret_cast<uint32_t*>(sm + GS_RMIN);
    if (tid < 128) rmin[tid] = 0x7F800000u;

    float szi[4];
    #pragma unroll
    for (int mt_i = 0; mt_i < 2; mt_i++)
        #pragma unroll
        for (int h = 0; h < 2; h++)
            szi[mt_i * 2 + h] = g_szi[rowBase + wm * 32 + mt_i * 16 + h * 8 + (lane >> 2)];
    __syncthreads();

    const float4* af4 = reinterpret_cast<const float4*>(g_af);
    const float4* bf4 = reinterpret_cast<const float4*>(g_bf);

    float C[2][8][4];

    #pragma unroll 1
    for (int nb = 0; nb < 8; nb++) {
        #pragma unroll
        for (int m = 0; m < 2; m++)
            #pragma unroll
            for (int j = 0; j < 8; j++)
                #pragma unroll
                for (int q = 0; q < 4; q++) C[m][j][q] = 0.0f;

        // stage chunk 0
        {
            const float4* asrc = af4 + ((size_t)blockIdx.x * 32) * 256;
            const float4* bsrc = bf4 + ((size_t)nb * 32) * 256;
            #pragma unroll
            for (int i = 0; i < 4; i++) {
                cp16(sb + GS_A0 + (i * 256 + tid) * 16, asrc + i * 256 + tid);
                cp16(sb + GS_B0 + (i * 256 + tid) * 16, bsrc + i * 256 + tid);
            }
            CP_COMMIT();
        }

        #pragma unroll 1
        for (int kc = 0; kc < 8; kc++) {
            if (kc < 7) {
                int nbuf = (kc + 1) & 1;
                const float4* asrc = af4 + ((size_t)blockIdx.x * 32 + (kc + 1) * 4) * 256;
                const float4* bsrc = bf4 + ((size_t)nb * 32 + (kc + 1) * 4) * 256;
                uint32_t abase = sb + (nbuf ? GS_A1 : GS_A0);
                uint32_t bbase = sb + (nbuf ? GS_B1 : GS_B0);
                #pragma unroll
                for (int i = 0; i < 4; i++) {
                    cp16(abase + (i * 256 + tid) * 16, asrc + i * 256 + tid);
                    cp16(bbase + (i * 256 + tid) * 16, bsrc + i * 256 + tid);
                }
                CP_COMMIT();
                CP_WAIT1();
            } else {
                CP_WAIT0();
            }
            __syncthreads();

            const char* Ab = sm + ((kc & 1) ? GS_A1 : GS_A0);
            const char* Bb = sm + ((kc & 1) ? GS_B1 : GS_B0);
            #pragma unroll
            for (int ks = 0; ks < 4; ks++) {
                uint4 a0 = *reinterpret_cast<const uint4*>(
                    Ab + ((ks * 8 + wm * 2 + 0) * 32 + lane) * 16);
                uint4 a1 = *reinterpret_cast<const uint4*>(
                    Ab + ((ks * 8 + wm * 2 + 1) * 32 + lane) * 16);
                #pragma unroll
                for (int j = 0; j < 8; j++) {
                    uint2 b = *reinterpret_cast<const uint2*>(
                        Bb + ((ks * 16 + wn * 8 + j) * 32 + lane) * 8);
                    mma_tf32(C[0][j], a0, b);
                    mma_tf32(C[1][j], a1, b);
                }
            }
            __syncthreads();
        }

        // epilogue: approx dist, store + per-row min
        #pragma unroll
        for (int mt_i = 0; mt_i < 2; mt_i++) {
            int rloc0 = wm * 32 + mt_i * 16 + (lane >> 2);
            float m0 = 3.0e38f, m1 = 3.0e38f;
            float s0 = szi[mt_i * 2], s1 = szi[mt_i * 2 + 1];
            #pragma unroll
            for (int j = 0; j < 8; j++) {
                int colb = nb * 128 + wn * 64 + j * 8 + (lane & 3) * 2;
                float se0 = se_sm[colb], se1 = se_sm[colb + 1];
                float d00 = fmaf(-2.0f, C[mt_i][j][0], s0 + se0);
                float d01 = fmaf(-2.0f, C[mt_i][j][1], s0 + se1);
                float d10 = fmaf(-2.0f, C[mt_i][j][2], s1 + se0);
                float d11 = fmaf(-2.0f, C[mt_i][j][3], s1 + se1);
                *reinterpret_cast<float2*>(
                    g_adist + (size_t)(rowBase + rloc0) * KCODES + colb) =
                    make_float2(d00, d01);
                *reinterpret_cast<float2*>(
                    g_adist + (size_t)(rowBase + rloc0 + 8) * KCODES + colb) =
                    make_float2(d10, d11);
                m0 = fminf(m0, fminf(d00, d01));
                m1 = fminf(m1, fminf(d10, d11));
            }
            atomicMin(&rmin[rloc0],     __float_as_uint(m0));
            atomicMin(&rmin[rloc0 + 8], __float_as_uint(m1));
        }
    }

    __syncthreads();
    if (tid < 128) g_amin[rowBase + tid] = rmin[tid];
}

// ---- refine: exact fp32 dist for candidates, reference-exact argmin ----
__global__ void refine_kernel(const float* __restrict__ x,
                              const float* __restrict__ cb) {
    __shared__ int cnt[8];
    __shared__ int list[8][64];
    int w = threadIdx.x >> 5, lane = threadIdx.x & 31;
    int row = blockIdx.x * 8 + w;
    if (lane == 0) cnt[w] = 0;
    __syncwarp();

    float thr = __uint_as_float(g_amin[row]) + MARGIN;
    const float4* ad = reinterpret_cast<const float4*>(g_adist + (size_t)row * KCODES);
    #pragma unroll
    for (int i = 0; i < 8; i++) {
        float4 v = ad[i * 32 + lane];
        int base = i * 128 + lane * 4;
        if (v.x <= thr) { int p = atomicAdd(&cnt[w], 1); if (p < 64) list[w][p] = base; }
        if (v.y <= thr) { int p = atomicAdd(&cnt[w], 1); if (p < 64) list[w][p] = base + 1; }
        if (v.z <= thr) { int p = atomicAdd(&cnt[w], 1); if (p < 64) list[w][p] = base + 2; }
        if (v.w <= thr) { int p = atomicAdd(&cnt[w], 1); if (p < 64) list[w][p] = base + 3; }
    }
    __syncwarp();
    int n = cnt[w] < 64 ? cnt[w] : 64;

    float4 xa = *reinterpret_cast<const float4*>(x + (size_t)row * DIM + lane * 8);
    float4 xb = *reinterpret_cast<const float4*>(x + (size_t)row * DIM + lane * 8 + 4);
    float szi = g_szi[row];

    float bd = 3.0e38f;
    int bi = 0x7FFFFFFF;
    for (int k = 0; k < n; k++) {
        int c = list[w][k];
        float4 ea = *reinterpret_cast<const float4*>(cb + (size_t)c * DIM + lane * 8);
        float4 eb = *reinterpret_cast<const float4*>(cb + (size_t)c * DIM + lane * 8 + 4);
        float p = xa.x * ea.x;
        p = fmaf(xa.y, ea.y, p); p = fmaf(xa.z, ea.z, p); p = fmaf(xa.w, ea.w, p);
        p = fmaf(xb.x, eb.x, p); p = fmaf(xb.y, eb.y, p);
        p = fmaf(xb.z, eb.z, p); p = fmaf(xb.w, eb.w, p);
        #pragma unroll
        for (int off = 16; off > 0; off >>= 1) p += __shfl_xor_sync(0xffffffffu, p, off);
        // reference-exact epilogue: dist = fl(fl(szi+se) - fl(2*dot))
        float dist = __fsub_rn(__fadd_rn(szi, g_se[c]), __fmul_rn(2.0f, p));
        if (dist < bd || (dist == bd && c < bi)) { bd = dist; bi = c; }
    }
    if (lane == 0) g_idx[row] = bi;
}

// ---- gather + ST output + ssd + histogram ----
__global__ void gather_kernel(const float* __restrict__ x,
                              const float* __restrict__ cb,
                              float* __restrict__ out) {
    __shared__ double warpsum[8];
    int warp = threadIdx.x >> 5, lane = threadIdx.x & 31;
    int row = blockIdx.x * 8 + warp;
    int c = g_idx[row];
    if (lane == 0) atomicAdd(&g_counts[c], 1);

    const float4* x4 = reinterpret_cast<const float4*>(x) + (size_t)row * 64;
    const float4* q4 = reinterpret_cast<const float4*>(cb) + (size_t)c * 64;
    float4* o4 = reinterpret_cast<float4*>(out) + (size_t)row * 64;

    float ssd = 0.f;
    #pragma unroll
    for (int t = 0; t < 2; t++) {
        int j = lane + 32 * t;
        float4 xv = x4[j];
        float4 qv = q4[j];
        float4 d;
        d.x = __fsub_rn(qv.x, xv.x); d.y = __fsub_rn(qv.y, xv.y);
        d.z = __fsub_rn(qv.z, xv.z); d.w = __fsub_rn(qv.w, xv.w);
        float4 o;
        o.x = __fadd_rn(xv.x, d.x); o.y = __fadd_rn(xv.y, d.y);
        o.z = __fadd_rn(xv.z, d.z); o.w = __fadd_rn(xv.w, d.w);
        o4[j] = o;
        ssd += d.x * d.x + d.y * d.y + d.z * d.z + d.w * d.w;
    }
    #pragma unroll
    for (int off = 16; off > 0; off >>= 1) ssd += __shfl_xor_sync(0xffffffffu, ssd, off);
    if (lane == 0) warpsum[warp] = (double)ssd;
    __syncthreads();
    if (threadIdx.x == 0) {
        double s = 0.0;
        #pragma unroll
        for (int wq = 0; wq < 8; wq++) s += warpsum[wq];
        atomicAdd(&g_ssd, s);
    }
}

__global__ void finalize_kernel(float* __restrict__ out, int out_size) {
    __shared__ double red[1024];
    int t = threadIdx.x;
    float p = (float)g_counts[t] * (1.0f / (float)NROWS);
    red[t] = (double)(p * logf(p + 1e-10f));
    __syncthreads();
    for (int s = 512; s > 0; s >>= 1) {
        if (t < s) red[t] += red[t + s];
        __syncthreads();
    }
    if (t == 0) {
        float perp = expf(-(float)red[0]);
        float loss = (float)(g_ssd * (1.25 / (double)QELEMS));
        out[out_size - 2] = loss;
        out[out_size - 1] = perp;
    }
}

extern "C" void kernel_launch(void* const* d_in, const int* in_sizes, int n_in,
                              void* d_out, int out_size) {
    const float* x  = (const float*)d_in[0];
    const float* cb = (const float*)d_in[1];
    float* out = (float*)d_out;

    cudaFuncSetAttribute(gemm_screen_kernel,
                         cudaFuncAttributeMaxDynamicSharedMemorySize, GS_TOTAL);

    zero_kernel<<<1, 1024>>>();
    rowsq_kernel<<<NROWS / 256, 256>>>(x);
    codesq_kernel<<<KCODES / 256, 256>>>(cb);
    packA_kernel<<<QELEMS / 4 / 256, 256>>>(x);
    packB_kernel<<<KCODES * DIM / 2 / 256, 256>>>(cb);
    gemm_screen_kernel<<<NROWS / 128, 256, GS_TOTAL>>>();
    refine_kernel<<<NROWS / 8, 256>>>(x, cb);
    gather_kernel<<<NROWS / 8, 256>>>(x, cb, out);
    finalize_kernel<<<1, 1024>>>(out, out_size);
}

// round 7
// speedup vs baseline: 2.6344x; 1.0155x over previous
#include <cuda_runtime.h>
#include <cstdint>

#define NROWS  32768
#define KCODES 1024
#define DIM    256
#define QELEMS (NROWS * DIM)
#define MARGIN 2.0e-3f
#define CAP    64

// GEMM smem layout (bytes)
#define GS_A0    0
#define GS_A1    16384
#define GS_B0    32768
#define GS_B1    49152
#define GS_SE    65536
#define GS_RMIN  69632       // 128 u32
#define GS_CCNT  70144       // 128 int
#define GS_CIDX  70656       // 128*64 int = 32KB
#define GS_TOTAL 103424

// ---- scratch (static device globals) ----
__device__ int      g_idx[NROWS];
__device__ float    g_se[KCODES];
__device__ float    g_szi[NROWS];
__device__ int      g_counts[KCODES];
__device__ double   g_ssd;
__device__ uint32_t g_af[QELEMS];            // tf32-packed A fragments
__device__ uint32_t g_bf[KCODES * DIM];      // tf32-packed B fragments
__device__ int      g_ccnt[NROWS];
__device__ int      g_cidx[(size_t)NROWS * CAP];

__device__ __forceinline__ uint32_t smem_u32(const void* p) {
    uint32_t a;
    asm("{ .reg .u64 t; cvta.to.shared.u64 t, %1; cvt.u32.u64 %0, t; }"
        : "=r"(a) : "l"(p));
    return a;
}
__device__ __forceinline__ uint32_t to_tf32(float f) {
    uint32_t r;
    asm("cvt.rna.tf32.f32 %0, %1;" : "=r"(r) : "f"(f));
    return r;
}
__device__ __forceinline__ void cp16(uint32_t s, const void* g) {
    asm volatile("cp.async.cg.shared.global [%0], [%1], 16;" :: "r"(s), "l"(g));
}
#define CP_COMMIT() asm volatile("cp.async.commit_group;" ::: "memory")
#define CP_WAIT1()  asm volatile("cp.async.wait_group 1;" ::: "memory")
#define CP_WAIT0()  asm volatile("cp.async.wait_group 0;" ::: "memory")

__device__ __forceinline__ void mma_tf32(float* c, const uint4& a, const uint2& b) {
    asm volatile(
        "mma.sync.aligned.m16n8k8.row.col.f32.tf32.tf32.f32 "
        "{%0,%1,%2,%3}, {%4,%5,%6,%7}, {%8,%9}, {%0,%1,%2,%3};"
        : "+f"(c[0]), "+f"(c[1]), "+f"(c[2]), "+f"(c[3])
        : "r"(a.x), "r"(a.y), "r"(a.z), "r"(a.w), "r"(b.x), "r"(b.y));
}

// ---- reference-exact sequential fp32 sumsq (DO NOT CHANGE ORDER) ----
__global__ void rowsq_kernel(const float* __restrict__ x) {
    int row = blockIdx.x * blockDim.x + threadIdx.x;
    if (row >= NROWS) return;
    const float4* p = reinterpret_cast<const float4*>(x) + (size_t)row * (DIM / 4);
    float s = 0.0f;
    #pragma unroll 4
    for (int i = 0; i < DIM / 4; i++) {
        float4 v = __ldg(p + i);
        s = __fadd_rn(s, __fmul_rn(v.x, v.x));
        s = __fadd_rn(s, __fmul_rn(v.y, v.y));
        s = __fadd_rn(s, __fmul_rn(v.z, v.z));
        s = __fadd_rn(s, __fmul_rn(v.w, v.w));
    }
    g_szi[row] = s;
}
// codesq + zeroing fused (exactly 1024 threads total)
__global__ void codesq_zero_kernel(const float* __restrict__ cb) {
    int code = blockIdx.x * blockDim.x + threadIdx.x;
    g_counts[code] = 0;
    if (code == 0) g_ssd = 0.0;
    const float4* p = reinterpret_cast<const float4*>(cb) + (size_t)code * (DIM / 4);
    float s = 0.0f;
    #pragma unroll 4
    for (int i = 0; i < DIM / 4; i++) {
        float4 v = __ldg(p + i);
        s = __fadd_rn(s, __fmul_rn(v.x, v.x));
        s = __fadd_rn(s, __fmul_rn(v.y, v.y));
        s = __fadd_rn(s, __fmul_rn(v.z, v.z));
        s = __fadd_rn(s, __fmul_rn(v.w, v.w));
    }
    g_se[code] = s;
}

// ---- pack A fragments: [mb][ks][mt][lane]{(r,c),(r+8,c),(r,c+4),(r+8,c+4)} ----
__global__ void packA_kernel(const float* __restrict__ x) {
    int t = blockIdx.x * 256 + threadIdx.x;
    int lane = t & 31, mt = (t >> 5) & 7, ks = (t >> 8) & 31, mb = t >> 13;
    int row = mb * 128 + mt * 16 + (lane >> 2);
    int d = ks * 8 + (lane & 3);
    const float* xr = x + (size_t)row * DIM + d;
    uint4 o;
    o.x = to_tf32(xr[0]);
    o.y = to_tf32(xr[8 * DIM]);
    o.z = to_tf32(xr[4]);
    o.w = to_tf32(xr[8 * DIM + 4]);
    reinterpret_cast<uint4*>(g_af)[t] = o;
}
// ---- pack B fragments ----
__global__ void packB_kernel(const float* __restrict__ cb) {
    int t = blockIdx.x * 256 + threadIdx.x;
    int lane = t & 31, nt = (t >> 5) & 15, ks = (t >> 9) & 31, nb = t >> 14;
    int c = nb * 128 + nt * 8 + (lane >> 2);
    int d = ks * 8 + (lane & 3);
    uint2 o;
    o.x = to_tf32(cb[(size_t)c * DIM + d]);
    o.y = to_tf32(cb[(size_t)c * DIM + d + 4]);
    reinterpret_cast<uint2*>(g_bf)[t] = o;
}

// ---- screening GEMM + fused candidate selection (no dist materialization) ----
__global__ __launch_bounds__(256, 2)
void gemm_screen_kernel() {
    extern __shared__ char sm[];
    const uint32_t sb = smem_u32(sm);
    const int tid = threadIdx.x;
    const int w = tid >> 5, lane = tid & 31;
    const int wm = w & 3, wn = w >> 2;
    const int rowBase = blockIdx.x * 128;

    float* se_sm = reinterpret_cast<float*>(sm + GS_SE);
    uint32_t* rmin = reinterpret_cast<uint32_t*>(sm + GS_RMIN);
    int* ccnt = reinterpret_cast<int*>(sm + GS_CCNT);
    int* cidx = reinterpret_cast<int*>(sm + GS_CIDX);

    #pragma unroll
    for (int i = 0; i < 4; i++) se_sm[i * 256 + tid] = g_se[i * 256 + tid];
    if (tid < 128) { rmin[tid] = 0x7F800000u; ccnt[tid] = 0; }

    float szi[4];
    #pragma unroll
    for (int mt_i = 0; mt_i < 2; mt_i++)
        #pragma unroll
        for (int h = 0; h < 2; h++)
            szi[mt_i * 2 + h] = g_szi[rowBase + wm * 32 + mt_i * 16 + h * 8 + (lane >> 2)];
    __syncthreads();

    const float4* af4 = reinterpret_cast<const float4*>(g_af);
    const float4* bf4 = reinterpret_cast<const float4*>(g_bf);

    float C[2][8][4];

    #pragma unroll 1
    for (int nb = 0; nb < 8; nb++) {
        #pragma unroll
        for (int m = 0; m < 2; m++)
            #pragma unroll
            for (int j = 0; j < 8; j++)
                #pragma unroll
                for (int q = 0; q < 4; q++) C[m][j][q] = 0.0f;

        {   // stage chunk 0
            const float4* asrc = af4 + ((size_t)blockIdx.x * 32) * 256;
            const float4* bsrc = bf4 + ((size_t)nb * 32) * 256;
            #pragma unroll
            for (int i = 0; i < 4; i++) {
                cp16(sb + GS_A0 + (i * 256 + tid) * 16, asrc + i * 256 + tid);
                cp16(sb + GS_B0 + (i * 256 + tid) * 16, bsrc + i * 256 + tid);
            }
            CP_COMMIT();
        }

        #pragma unroll 1
        for (int kc = 0; kc < 8; kc++) {
            if (kc < 7) {
                int nbuf = (kc + 1) & 1;
                const float4* asrc = af4 + ((size_t)blockIdx.x * 32 + (kc + 1) * 4) * 256;
                const float4* bsrc = bf4 + ((size_t)nb * 32 + (kc + 1) * 4) * 256;
                uint32_t abase = sb + (nbuf ? GS_A1 : GS_A0);
                uint32_t bbase = sb + (nbuf ? GS_B1 : GS_B0);
                #pragma unroll
                for (int i = 0; i < 4; i++) {
                    cp16(abase + (i * 256 + tid) * 16, asrc + i * 256 + tid);
                    cp16(bbase + (i * 256 + tid) * 16, bsrc + i * 256 + tid);
                }
                CP_COMMIT();
                CP_WAIT1();
            } else {
                CP_WAIT0();
            }
            __syncthreads();

            const char* Ab = sm + ((kc & 1) ? GS_A1 : GS_A0);
            const char* Bb = sm + ((kc & 1) ? GS_B1 : GS_B0);
            #pragma unroll
            for (int ks = 0; ks < 4; ks++) {
                uint4 a0 = *reinterpret_cast<const uint4*>(
                    Ab + ((ks * 8 + wm * 2 + 0) * 32 + lane) * 16);
                uint4 a1 = *reinterpret_cast<const uint4*>(
                    Ab + ((ks * 8 + wm * 2 + 1) * 32 + lane) * 16);
                #pragma unroll
                for (int j = 0; j < 8; j++) {
                    uint2 b = *reinterpret_cast<const uint2*>(
                        Bb + ((ks * 16 + wn * 8 + j) * 32 + lane) * 8);
                    mma_tf32(C[0][j], a0, b);
                    mma_tf32(C[1][j], a1, b);
                }
            }
            __syncthreads();
        }

        // epilogue: dists in regs; candidate = d <= min(row_min_cached, local_min) + MARGIN
        #pragma unroll
        for (int mt_i = 0; mt_i < 2; mt_i++) {
            int rl0 = wm * 32 + mt_i * 16 + (lane >> 2);
            int rl1 = rl0 + 8;
            float s0 = szi[mt_i * 2], s1 = szi[mt_i * 2 + 1];
            float d0v[16], d1v[16];
            float lm0 = 3.0e38f, lm1 = 3.0e38f;
            #pragma unroll
            for (int j = 0; j < 8; j++) {
                float se0 = se_sm[nb * 128 + wn * 64 + j * 8 + (lane & 3) * 2];
                float se1 = se_sm[nb * 128 + wn * 64 + j * 8 + (lane & 3) * 2 + 1];
                d0v[j * 2]     = fmaf(-2.0f, C[mt_i][j][0], s0 + se0);
                d0v[j * 2 + 1] = fmaf(-2.0f, C[mt_i][j][1], s0 + se1);
                d1v[j * 2]     = fmaf(-2.0f, C[mt_i][j][2], s1 + se0);
                d1v[j * 2 + 1] = fmaf(-2.0f, C[mt_i][j][3], s1 + se1);
                lm0 = fminf(lm0, fminf(d0v[j * 2], d0v[j * 2 + 1]));
                lm1 = fminf(lm1, fminf(d1v[j * 2], d1v[j * 2 + 1]));
            }
            float cm0 = fminf(__uint_as_float(rmin[rl0]), lm0);
            float cm1 = fminf(__uint_as_float(rmin[rl1]), lm1);
            atomicMin(&rmin[rl0], __float_as_uint(lm0));
            atomicMin(&rmin[rl1], __float_as_uint(lm1));
            float t0 = cm0 + MARGIN, t1 = cm1 + MARGIN;
            #pragma unroll
            for (int q = 0; q < 16; q++) {
                int code = nb * 128 + wn * 64 + (q >> 1) * 8 + (lane & 3) * 2 + (q & 1);
                if (d0v[q] <= t0) {
                    int p = atomicAdd(&ccnt[rl0], 1);
                    if (p < CAP) cidx[rl0 * CAP + p] = code;
                }
                if (d1v[q] <= t1) {
                    int p = atomicAdd(&ccnt[rl1], 1);
                    if (p < CAP) cidx[rl1 * CAP + p] = code;
                }
            }
        }
    }

    __syncthreads();
    if (tid < 128) g_ccnt[rowBase + tid] = ccnt[tid];
    // copy candidate lists out (only valid prefix matters)
    #pragma unroll
    for (int i = 0; i < 32; i++) {
        int li = i * 256 + tid;                     // 0..8191
        int r = li >> 6, k = li & 63;
        if (k < ccnt[r])
            g_cidx[(size_t)(rowBase + r) * CAP + k] = cidx[r * CAP + k];
    }
}

// ---- fused refine (exact argmin over candidates) + gather/output/ssd/hist ----
__global__ void refine_gather_kernel(const float* __restrict__ x,
                                     const float* __restrict__ cb,
                                     float* __restrict__ out) {
    __shared__ double warpsum[8];
    int w = threadIdx.x >> 5, lane = threadIdx.x & 31;
    int row = blockIdx.x * 8 + w;

    float4 xa = *reinterpret_cast<const float4*>(x + (size_t)row * DIM + lane * 8);
    float4 xb = *reinterpret_cast<const float4*>(x + (size_t)row * DIM + lane * 8 + 4);
    float szi = g_szi[row];
    int cnt = g_ccnt[row];

    float bd = 3.0e38f;
    int bi = 0x7FFFFFFF;
    if (cnt <= CAP) {
        for (int k = 0; k < cnt; k++) {
            int c = g_cidx[(size_t)row * CAP + k];
            float4 ea = *reinterpret_cast<const float4*>(cb + (size_t)c * DIM + lane * 8);
            float4 eb = *reinterpret_cast<const float4*>(cb + (size_t)c * DIM + lane * 8 + 4);
            float p = xa.x * ea.x;
            p = fmaf(xa.y, ea.y, p); p = fmaf(xa.z, ea.z, p); p = fmaf(xa.w, ea.w, p);
            p = fmaf(xb.x, eb.x, p); p = fmaf(xb.y, eb.y, p);
            p = fmaf(xb.z, eb.z, p); p = fmaf(xb.w, eb.w, p);
            #pragma unroll
            for (int off = 16; off > 0; off >>= 1) p += __shfl_xor_sync(0xffffffffu, p, off);
            float dist = __fsub_rn(__fadd_rn(szi, g_se[c]), __fmul_rn(2.0f, p));
            if (dist < bd || (dist == bd && c < bi)) { bd = dist; bi = c; }
        }
    } else {
        // overflow fallback: exact scan of all codes (expected never)
        for (int c = 0; c < KCODES; c++) {
            float4 ea = *reinterpret_cast<const float4*>(cb + (size_t)c * DIM + lane * 8);
            float4 eb = *reinterpret_cast<const float4*>(cb + (size_t)c * DIM + lane * 8 + 4);
            float p = xa.x * ea.x;
            p = fmaf(xa.y, ea.y, p); p = fmaf(xa.z, ea.z, p); p = fmaf(xa.w, ea.w, p);
            p = fmaf(xb.x, eb.x, p); p = fmaf(xb.y, eb.y, p);
            p = fmaf(xb.z, eb.z, p); p = fmaf(xb.w, eb.w, p);
            #pragma unroll
            for (int off = 16; off > 0; off >>= 1) p += __shfl_xor_sync(0xffffffffu, p, off);
            float dist = __fsub_rn(__fadd_rn(szi, g_se[c]), __fmul_rn(2.0f, p));
            if (dist < bd) { bd = dist; bi = c; }     // ascending scan: '<' keeps lowest
        }
    }

    if (lane == 0) { g_idx[row] = bi; atomicAdd(&g_counts[bi], 1); }

    // gather + straight-through output + ssd (reference rounding: o = x + (q-x))
    float4 qa = *reinterpret_cast<const float4*>(cb + (size_t)bi * DIM + lane * 8);
    float4 qb = *reinterpret_cast<const float4*>(cb + (size_t)bi * DIM + lane * 8 + 4);
    float4 da, db, oa, ob;
    da.x = __fsub_rn(qa.x, xa.x); da.y = __fsub_rn(qa.y, xa.y);
    da.z = __fsub_rn(qa.z, xa.z); da.w = __fsub_rn(qa.w, xa.w);
    db.x = __fsub_rn(qb.x, xb.x); db.y = __fsub_rn(qb.y, xb.y);
    db.z = __fsub_rn(qb.z, xb.z); db.w = __fsub_rn(qb.w, xb.w);
    oa.x = __fadd_rn(xa.x, da.x); oa.y = __fadd_rn(xa.y, da.y);
    oa.z = __fadd_rn(xa.z, da.z); oa.w = __fadd_rn(xa.w, da.w);
    ob.x = __fadd_rn(xb.x, db.x); ob.y = __fadd_rn(xb.y, db.y);
    ob.z = __fadd_rn(xb.z, db.z); ob.w = __fadd_rn(xb.w, db.w);
    *reinterpret_cast<float4*>(out + (size_t)row * DIM + lane * 8)     = oa;
    *reinterpret_cast<float4*>(out + (size_t)row * DIM + lane * 8 + 4) = ob;

    float ssd = da.x * da.x + da.y * da.y + da.z * da.z + da.w * da.w
              + db.x * db.x + db.y * db.y + db.z * db.z + db.w * db.w;
    #pragma unroll
    for (int off = 16; off > 0; off >>= 1) ssd += __shfl_xor_sync(0xffffffffu, ssd, off);
    if (lane == 0) warpsum[w] = (double)ssd;
    __syncthreads();
    if (threadIdx.x == 0) {
        double s = 0.0;
        #pragma unroll
        for (int q = 0; q < 8; q++) s += warpsum[q];
        atomicAdd(&g_ssd, s);
    }
}

__global__ void finalize_kernel(float* __restrict__ out, int out_size) {
    __shared__ double red[1024];
    int t = threadIdx.x;
    float p = (float)g_counts[t] * (1.0f / (float)NROWS);
    red[t] = (double)(p * logf(p + 1e-10f));
    __syncthreads();
    for (int s = 512; s > 0; s >>= 1) {
        if (t < s) red[t] += red[t + s];
        __syncthreads();
    }
    if (t == 0) {
        float perp = expf(-(float)red[0]);
        float loss = (float)(g_ssd * (1.25 / (double)QELEMS));
        out[out_size - 2] = loss;
        out[out_size - 1] = perp;
    }
}

extern "C" void kernel_launch(void* const* d_in, const int* in_sizes, int n_in,
                              void* d_out, int out_size) {
    const float* x  = (const float*)d_in[0];
    const float* cb = (const float*)d_in[1];
    float* out = (float*)d_out;

    cudaFuncSetAttribute(gemm_screen_kernel,
                         cudaFuncAttributeMaxDynamicSharedMemorySize, GS_TOTAL);

    codesq_zero_kernel<<<KCODES / 256, 256>>>(cb);
    rowsq_kernel<<<NROWS / 256, 256>>>(x);
    packA_kernel<<<QELEMS / 4 / 256, 256>>>(x);
    packB_kernel<<<KCODES * DIM / 2 / 256, 256>>>(cb);
    gemm_screen_kernel<<<NROWS / 128, 256, GS_TOTAL>>>();
    refine_gather_kernel<<<NROWS / 8, 256>>>(x, cb, out);
    finalize_kernel<<<1, 1024>>>(out, out_size);
}